// round 5
// baseline (speedup 1.0000x reference)
#include <cuda_runtime.h>
#include <cstdint>

#define NUM_SEG 2048
#define EPS 1e-6f
#define RPB 64                 // rows per block (1024 float4)
#define TPB 256

// State, grouped so two byte-fill memsets initialize everything:
//   g_ff : [g_min | g_start]           -> memset 0xFF
//   g_00 : [g_max | g_done | g_end]    -> memset 0x00
__device__ unsigned int g_ff[2 * NUM_SEG];
__device__ unsigned int g_00[3 * NUM_SEG];

#define G_MIN   (g_ff)
#define G_START (g_ff + NUM_SEG)
#define G_MAX   (g_00)
#define G_DONE  (g_00 + NUM_SEG)
#define G_END   (g_00 + 2 * NUM_SEG)

__device__ __forceinline__ unsigned int f2ord(float f) {
    unsigned int u = __float_as_uint(f);
    return (u & 0x80000000u) ? ~u : (u | 0x80000000u);
}
__device__ __forceinline__ float ord2f(unsigned int u) {
    u = (u & 0x80000000u) ? (u ^ 0x80000000u) : ~u;
    return __uint_as_float(u);
}
__device__ __forceinline__ float f4min(float4 v) { return fminf(fminf(v.x, v.y), fminf(v.z, v.w)); }
__device__ __forceinline__ float f4max(float4 v) { return fmaxf(fmaxf(v.x, v.y), fmaxf(v.z, v.w)); }
__device__ __forceinline__ unsigned int vload(const unsigned int* p) {
    return *(const volatile unsigned int*)p;
}
// Spin until segment s is final (all rows contributed). L2-coherent volatile polls.
__device__ __forceinline__ void spin_seg(int s) {
    for (;;) {
        unsigned int st = vload(&G_START[s]);
        unsigned int en = vload(&G_END[s]);
        if (st != 0xFFFFFFFFu && en != 0u && vload(&G_DONE[s]) == en - st) return;
        __nanosleep(100);
    }
}

// Single pass: block loads 64 rows (4 front-batched float4/thread) into
// registers, REDs its local min/max, publishes row-count + segment start/end
// rows, spin-waits for its segments' finality, then normalizes the data it
// STILL HOLDS IN REGISTERS. x is read from DRAM exactly once: total traffic
// ~517 MB vs 768 MB for the two-pass version.
//
// Deadlock safety: a block waits only on segments spanning <=~11 neighboring
// blocks; concurrency is ~1000+ CTAs and phase A (load+publish) never blocks,
// so contributors are always scheduled and completers always exist.
__global__ void __launch_bounds__(TPB) mm_fused(const float4* __restrict__ x4,
                                                const int* __restrict__ seg,
                                                float4* __restrict__ o4,
                                                int nrows) {
    const int t        = threadIdx.x;
    const int lane     = t & 31;
    const int w        = t >> 5;
    const int base_row = blockIdx.x * RPB;
    const int base4    = base_row * 16;
    const bool full    = (base_row + RPB <= nrows);
    const int last_row = min(base_row + RPB, nrows) - 1;

    const int s0 = __ldg(&seg[base_row]);
    const int sL = __ldg(&seg[last_row]);
    const bool own_start = (base_row == 0) || (__ldg(&seg[base_row - 1]) < s0);
    const bool own_end   = (base_row + RPB >= nrows) || (__ldg(&seg[base_row + RPB]) > sL);

    if (s0 == sL && full) {
        // ---- fast path (~87% of blocks): whole block is one segment ----
        float4 v0 = __ldcs(&x4[base4 + t]);
        float4 v1 = __ldcs(&x4[base4 + 256 + t]);
        float4 v2 = __ldcs(&x4[base4 + 512 + t]);
        float4 v3 = __ldcs(&x4[base4 + 768 + t]);
        float mn = fminf(fminf(f4min(v0), f4min(v1)), fminf(f4min(v2), f4min(v3)));
        float mx = fmaxf(fmaxf(f4max(v0), f4max(v1)), fmaxf(f4max(v2), f4max(v3)));
        #pragma unroll
        for (int o = 16; o > 0; o >>= 1) {
            mn = fminf(mn, __shfl_down_sync(0xFFFFFFFFu, mn, o));
            mx = fmaxf(mx, __shfl_down_sync(0xFFFFFFFFu, mx, o));
        }
        __shared__ float wmin[8], wmax[8];
        __shared__ float2 sh_p;
        if (lane == 0) { wmin[w] = mn; wmax[w] = mx; }
        __syncthreads();
        if (w == 0 && lane < 8) {
            mn = wmin[lane];
            mx = wmax[lane];
            #pragma unroll
            for (int o = 4; o > 0; o >>= 1) {
                mn = fminf(mn, __shfl_down_sync(0x000000FFu, mn, o));
                mx = fmaxf(mx, __shfl_down_sync(0x000000FFu, mx, o));
            }
            if (lane == 0) {
                // publish (release)
                atomicMin(&G_MIN[s0], f2ord(mn));
                atomicMax(&G_MAX[s0], f2ord(mx));
                if (own_start) atomicExch(&G_START[s0], (unsigned int)base_row);
                if (own_end)   atomicExch(&G_END[s0],   (unsigned int)(base_row + RPB));
                __threadfence();
                atomicAdd(&G_DONE[s0], (unsigned int)RPB);
                // wait for segment finality (acquire)
                spin_seg(s0);
                __threadfence();
                float gmn = ord2f(__ldcg(&G_MIN[s0]));   // __ldcg: bypass (non-coherent) L1
                float gmx = ord2f(__ldcg(&G_MAX[s0]));
                sh_p = make_float2(gmn, 1.0f / (gmx - gmn + EPS));
            }
        }
        __syncthreads();
        const float2 p = sh_p;
        float4 r0, r1, r2, r3;
        r0.x=(v0.x-p.x)*p.y; r0.y=(v0.y-p.x)*p.y; r0.z=(v0.z-p.x)*p.y; r0.w=(v0.w-p.x)*p.y;
        r1.x=(v1.x-p.x)*p.y; r1.y=(v1.y-p.x)*p.y; r1.z=(v1.z-p.x)*p.y; r1.w=(v1.w-p.x)*p.y;
        r2.x=(v2.x-p.x)*p.y; r2.y=(v2.y-p.x)*p.y; r2.z=(v2.z-p.x)*p.y; r2.w=(v2.w-p.x)*p.y;
        r3.x=(v3.x-p.x)*p.y; r3.y=(v3.y-p.x)*p.y; r3.z=(v3.z-p.x)*p.y; r3.w=(v3.w-p.x)*p.y;
        __stcs(&o4[base4 + t],       r0);
        __stcs(&o4[base4 + 256 + t], r1);
        __stcs(&o4[base4 + 512 + t], r2);
        __stcs(&o4[base4 + 768 + t], r3);
        return;
    }

    // ---- slow path: block contains segment boundaries (or grid tail) ----
    __shared__ unsigned int sl_min[RPB], sl_max[RPB], sl_cnt[RPB];
    __shared__ float2       sl_prm[RPB];
    if (t < RPB) { sl_min[t] = 0xFFFFFFFFu; sl_max[t] = 0u; sl_cnt[t] = 0u; }
    __syncthreads();

    float4 v[4];
    int    sg[4];
    bool   ok[4];
    #pragma unroll
    for (int k = 0; k < 4; ++k) {
        const int idx = base4 + k * 256 + t;
        const int row = idx >> 4;
        ok[k] = (row < nrows);
        if (ok[k]) {
            v[k]  = __ldcs(&x4[idx]);
            sg[k] = __ldg(&seg[row]);
        }
    }
    #pragma unroll
    for (int k = 0; k < 4; ++k) {
        if (ok[k]) {
            const int slot = sg[k] - s0;
            atomicMin(&sl_min[slot], f2ord(f4min(v[k])));
            atomicMax(&sl_max[slot], f2ord(f4max(v[k])));
        }
    }
    if ((t & 15) == 0) {     // one thread of the 16 sharing each row counts it
        #pragma unroll
        for (int k = 0; k < 4; ++k)
            if (ok[k]) atomicAdd(&sl_cnt[sg[k] - s0], 1u);
    }
    __syncthreads();

    // Publish each touched segment: RED min/max, start/end rows if owned here,
    // fence, then row-count contribution.
    if (t < RPB && sl_cnt[t] > 0) {
        const int s = s0 + t;
        atomicMin(&G_MIN[s], sl_min[t]);
        atomicMax(&G_MAX[s], sl_max[t]);
        // first local row of slot t = base_row + prefix of counts (seg sorted)
        unsigned int pre = 0;
        for (int j = 0; j < t; ++j) pre += sl_cnt[j];
        const unsigned int frow = (unsigned int)base_row + pre;
        const unsigned int erow = frow + sl_cnt[t];
        const bool st_own = (t > 0) || own_start;   // segment starts inside block
        const bool en_own = (s < sL) || own_end;    // segment ends inside block
        if (st_own) atomicExch(&G_START[s], frow);
        if (en_own) atomicExch(&G_END[s], erow);
        __threadfence();
        atomicAdd(&G_DONE[s], sl_cnt[t]);
    }
    __syncthreads();

    // Only s0 and sL can extend beyond this block; interior segments are
    // final after our own contribution (same-thread program order + fence).
    if (t == 0) spin_seg(s0);
    if (t == 1 && sL != s0) spin_seg(sL);
    __syncthreads();
    __threadfence();

    if (t < RPB && sl_cnt[t] > 0) {
        const int s = s0 + t;
        const float gmn = ord2f(__ldcg(&G_MIN[s]));
        const float gmx = ord2f(__ldcg(&G_MAX[s]));
        sl_prm[t] = make_float2(gmn, 1.0f / (gmx - gmn + EPS));
    }
    __syncthreads();

    #pragma unroll
    for (int k = 0; k < 4; ++k) {
        if (ok[k]) {
            const float2 p = sl_prm[sg[k] - s0];
            float4 r;
            r.x=(v[k].x-p.x)*p.y; r.y=(v[k].y-p.x)*p.y;
            r.z=(v[k].z-p.x)*p.y; r.w=(v[k].w-p.x)*p.y;
            __stcs(&o4[base4 + k * 256 + t], r);
        }
    }
}

extern "C" void kernel_launch(void* const* d_in, const int* in_sizes, int n_in,
                              void* d_out, int out_size) {
    const float* x   = (const float*)d_in[0];
    const int*   seg = (const int*)d_in[1];
    float*       out = (float*)d_out;

    int nrows = in_sizes[1];          // 1,000,000

    void* pff = nullptr; void* p00 = nullptr;
    cudaGetSymbolAddress(&pff, g_ff);
    cudaGetSymbolAddress(&p00, g_00);
    cudaMemsetAsync(pff, 0xFF, 2 * NUM_SEG * sizeof(unsigned int), 0);
    cudaMemsetAsync(p00, 0x00, 3 * NUM_SEG * sizeof(unsigned int), 0);

    int blocks = (nrows + RPB - 1) / RPB;   // 15625
    mm_fused<<<blocks, TPB>>>((const float4*)x, seg, (float4*)out, nrows);
}

// round 6
// speedup vs baseline: 1.0335x; 1.0335x over previous
#include <cuda_runtime.h>
#include <cstdint>

#define NUM_SEG 2048
#define EPS 1e-6f
#define RPB 64                 // rows per block (1024 float4)
#define TPB 256

// State, grouped so two byte-fill memsets initialize everything:
//   g_ff : [g_min | g_start]           -> memset 0xFF
//   g_00 : [g_max | g_done | g_end]    -> memset 0x00
__device__ unsigned int g_ff[2 * NUM_SEG];
__device__ unsigned int g_00[3 * NUM_SEG];

#define G_MIN   (g_ff)
#define G_START (g_ff + NUM_SEG)
#define G_MAX   (g_00)
#define G_DONE  (g_00 + NUM_SEG)
#define G_END   (g_00 + 2 * NUM_SEG)

__device__ __forceinline__ unsigned int f2ord(float f) {
    unsigned int u = __float_as_uint(f);
    return (u & 0x80000000u) ? ~u : (u | 0x80000000u);
}
__device__ __forceinline__ float ord2f(unsigned int u) {
    u = (u & 0x80000000u) ? (u ^ 0x80000000u) : ~u;
    return __uint_as_float(u);
}
__device__ __forceinline__ float f4min(float4 v) { return fminf(fminf(v.x, v.y), fminf(v.z, v.w)); }
__device__ __forceinline__ float f4max(float4 v) { return fmaxf(fmaxf(v.x, v.y), fmaxf(v.z, v.w)); }
__device__ __forceinline__ unsigned int vload(const unsigned int* p) {
    return *(const volatile unsigned int*)p;
}
// Spin until segment s is final (all rows contributed). L2-coherent volatile polls.
__device__ __forceinline__ void spin_seg(int s) {
    for (;;) {
        unsigned int st = vload(&G_START[s]);
        unsigned int en = vload(&G_END[s]);
        if (st != 0xFFFFFFFFu && en != 0u && vload(&G_DONE[s]) == en - st) return;
        __nanosleep(64);
    }
}

// Single-pass, L2-reuse variant. Phase A: stream the block's 64 rows through
// min/max accumulators (no register-holding -> low regs, 8 CTAs/SM), publish
// via RED + release protocol. Spin on the block's (<=2 boundary) segments.
// Phase B: RE-READ the tile with __ldcg — the reuse window is a few µs
// (~25 MB of intervening chip traffic << 126 MB L2), so these hit L2 —
// normalize, streaming-store. DRAM traffic ~520 MB vs 768 MB two-pass.
__global__ void __launch_bounds__(TPB, 8) mm_fused(const float4* __restrict__ x4,
                                                   const int* __restrict__ seg,
                                                   float4* __restrict__ o4,
                                                   int nrows) {
    const int t        = threadIdx.x;
    const int lane     = t & 31;
    const int w        = t >> 5;
    const int base_row = blockIdx.x * RPB;
    const int base4    = base_row * 16;
    const bool full    = (base_row + RPB <= nrows);
    const int last_row = min(base_row + RPB, nrows) - 1;

    const int s0 = __ldg(&seg[base_row]);
    const int sL = __ldg(&seg[last_row]);
    const bool own_start = (base_row == 0) || (__ldg(&seg[base_row - 1]) < s0);
    const bool own_end   = (base_row + RPB >= nrows) || (__ldg(&seg[base_row + RPB]) > sL);

    if (s0 == sL && full) {
        // ---- fast path (~87% of blocks): whole block is one segment ----
        // Phase A: 4 front-batched loads, folded immediately (v regs die here).
        float4 v0 = __ldcg(&x4[base4 + t]);
        float4 v1 = __ldcg(&x4[base4 + 256 + t]);
        float4 v2 = __ldcg(&x4[base4 + 512 + t]);
        float4 v3 = __ldcg(&x4[base4 + 768 + t]);
        float mn = fminf(fminf(f4min(v0), f4min(v1)), fminf(f4min(v2), f4min(v3)));
        float mx = fmaxf(fmaxf(f4max(v0), f4max(v1)), fmaxf(f4max(v2), f4max(v3)));
        #pragma unroll
        for (int o = 16; o > 0; o >>= 1) {
            mn = fminf(mn, __shfl_down_sync(0xFFFFFFFFu, mn, o));
            mx = fmaxf(mx, __shfl_down_sync(0xFFFFFFFFu, mx, o));
        }
        __shared__ float wmin[8], wmax[8];
        __shared__ float2 sh_p;
        if (lane == 0) { wmin[w] = mn; wmax[w] = mx; }
        __syncthreads();
        if (w == 0 && lane < 8) {
            mn = wmin[lane];
            mx = wmax[lane];
            #pragma unroll
            for (int o = 4; o > 0; o >>= 1) {
                mn = fminf(mn, __shfl_down_sync(0x000000FFu, mn, o));
                mx = fmaxf(mx, __shfl_down_sync(0x000000FFu, mx, o));
            }
            if (lane == 0) {
                // publish (release)
                atomicMin(&G_MIN[s0], f2ord(mn));
                atomicMax(&G_MAX[s0], f2ord(mx));
                if (own_start) atomicExch(&G_START[s0], (unsigned int)base_row);
                if (own_end)   atomicExch(&G_END[s0],   (unsigned int)(base_row + RPB));
                __threadfence();
                atomicAdd(&G_DONE[s0], (unsigned int)RPB);
                // wait for segment finality (acquire)
                spin_seg(s0);
                __threadfence();
                float gmn = ord2f(__ldcg(&G_MIN[s0]));
                float gmx = ord2f(__ldcg(&G_MAX[s0]));
                sh_p = make_float2(gmn, 1.0f / (gmx - gmn + EPS));
            }
        }
        __syncthreads();
        const float2 p = sh_p;
        // Phase B: re-read (L2 hit), normalize, streaming store.
        float4 a0 = __ldcg(&x4[base4 + t]);
        float4 a1 = __ldcg(&x4[base4 + 256 + t]);
        float4 a2 = __ldcg(&x4[base4 + 512 + t]);
        float4 a3 = __ldcg(&x4[base4 + 768 + t]);
        float4 r0, r1, r2, r3;
        r0.x=(a0.x-p.x)*p.y; r0.y=(a0.y-p.x)*p.y; r0.z=(a0.z-p.x)*p.y; r0.w=(a0.w-p.x)*p.y;
        r1.x=(a1.x-p.x)*p.y; r1.y=(a1.y-p.x)*p.y; r1.z=(a1.z-p.x)*p.y; r1.w=(a1.w-p.x)*p.y;
        r2.x=(a2.x-p.x)*p.y; r2.y=(a2.y-p.x)*p.y; r2.z=(a2.z-p.x)*p.y; r2.w=(a2.w-p.x)*p.y;
        r3.x=(a3.x-p.x)*p.y; r3.y=(a3.y-p.x)*p.y; r3.z=(a3.z-p.x)*p.y; r3.w=(a3.w-p.x)*p.y;
        __stcs(&o4[base4 + t],       r0);
        __stcs(&o4[base4 + 256 + t], r1);
        __stcs(&o4[base4 + 512 + t], r2);
        __stcs(&o4[base4 + 768 + t], r3);
        return;
    }

    // ---- slow path: block contains segment boundaries (or grid tail) ----
    __shared__ unsigned int sl_min[RPB], sl_max[RPB], sl_cnt[RPB];
    __shared__ float2       sl_prm[RPB];
    if (t < RPB) { sl_min[t] = 0xFFFFFFFFu; sl_max[t] = 0u; sl_cnt[t] = 0u; }
    __syncthreads();

    // Phase A: load, fold into smem slot atomics (no register-holding).
    #pragma unroll
    for (int k = 0; k < 4; ++k) {
        const int idx = base4 + k * 256 + t;
        const int row = idx >> 4;
        if (row < nrows) {
            const float4 v = __ldcg(&x4[idx]);
            const int s = __ldg(&seg[row]);
            const int slot = s - s0;
            atomicMin(&sl_min[slot], f2ord(f4min(v)));
            atomicMax(&sl_max[slot], f2ord(f4max(v)));
            if ((t & 15) == 0) atomicAdd(&sl_cnt[slot], 1u);
        }
    }
    __syncthreads();

    // Publish each touched segment: RED min/max, start/end rows if owned here,
    // fence, then row-count contribution.
    if (t < RPB && sl_cnt[t] > 0) {
        const int s = s0 + t;
        atomicMin(&G_MIN[s], sl_min[t]);
        atomicMax(&G_MAX[s], sl_max[t]);
        unsigned int pre = 0;
        for (int j = 0; j < t; ++j) pre += sl_cnt[j];
        const unsigned int frow = (unsigned int)base_row + pre;
        const unsigned int erow = frow + sl_cnt[t];
        const bool st_own = (t > 0) || own_start;
        const bool en_own = (s < sL) || own_end;
        if (st_own) atomicExch(&G_START[s], frow);
        if (en_own) atomicExch(&G_END[s], erow);
        __threadfence();
        atomicAdd(&G_DONE[s], sl_cnt[t]);
    }
    __syncthreads();

    // Only s0 and sL can extend beyond this block.
    if (t == 0) spin_seg(s0);
    if (t == 1 && sL != s0) spin_seg(sL);
    __syncthreads();
    __threadfence();

    if (t < RPB && sl_cnt[t] > 0) {
        const int s = s0 + t;
        const float gmn = ord2f(__ldcg(&G_MIN[s]));
        const float gmx = ord2f(__ldcg(&G_MAX[s]));
        sl_prm[t] = make_float2(gmn, 1.0f / (gmx - gmn + EPS));
    }
    __syncthreads();

    // Phase B: re-read (L2 hit), normalize, store.
    #pragma unroll
    for (int k = 0; k < 4; ++k) {
        const int idx = base4 + k * 256 + t;
        const int row = idx >> 4;
        if (row < nrows) {
            const float4 v = __ldcg(&x4[idx]);
            const float2 p = sl_prm[__ldg(&seg[row]) - s0];
            float4 r;
            r.x=(v.x-p.x)*p.y; r.y=(v.y-p.x)*p.y;
            r.z=(v.z-p.x)*p.y; r.w=(v.w-p.x)*p.y;
            __stcs(&o4[idx], r);
        }
    }
}

extern "C" void kernel_launch(void* const* d_in, const int* in_sizes, int n_in,
                              void* d_out, int out_size) {
    const float* x   = (const float*)d_in[0];
    const int*   seg = (const int*)d_in[1];
    float*       out = (float*)d_out;

    int nrows = in_sizes[1];          // 1,000,000

    void* pff = nullptr; void* p00 = nullptr;
    cudaGetSymbolAddress(&pff, g_ff);
    cudaGetSymbolAddress(&p00, g_00);
    cudaMemsetAsync(pff, 0xFF, 2 * NUM_SEG * sizeof(unsigned int), 0);
    cudaMemsetAsync(p00, 0x00, 3 * NUM_SEG * sizeof(unsigned int), 0);

    int blocks = (nrows + RPB - 1) / RPB;   // 15625
    mm_fused<<<blocks, TPB>>>((const float4*)x, seg, (float4*)out, nrows);
}